// round 4
// baseline (speedup 1.0000x reference)
#include <cuda_runtime.h>
#include <math.h>

#define N_NODES_C 100000
#define N_PATHS_C 1000000
#define T_C 16
#define F_C 9
#define E_C 8000000

// Node record: 16 floats (64B): [0..8] = Re(log X_f), [9..15] = Im(log X_f) for f=1..7.
// Im at f=0 and f=8 is exactly 0 (rfft of real input), so it is not stored.
__device__ float4 g_node_table[N_NODES_C * 4];
__device__ int g_seg_start[N_PATHS_C + 1];

// ---------------------------------------------------------------------------
// Kernel A: per-node IRF -> rfft(16) -> complex log, packed 64B per node.
// ---------------------------------------------------------------------------
__global__ __launch_bounds__(128)
void node_irf_kernel(const float* __restrict__ params, int n_nodes) {
    int n = blockIdx.x * blockDim.x + threadIdx.x;
    if (n >= n_nodes) return;

    float k = params[n] + 0.5f;
    float inv_k = 1.0f / k;

    float irf[T_C];
#pragma unroll
    for (int t = 0; t < T_C; t++) {
        irf[t] = expf(-(float)t * inv_k) * inv_k;
    }

    float rec[16];
#pragma unroll
    for (int f = 0; f < F_C; f++) {
        float sr = 0.0f, si = 0.0f;
#pragma unroll
        for (int t = 0; t < T_C; t++) {
            // rfft twiddle: exp(-2*pi*i*f*t/16) -> angle fraction f*t/8 of pi
            float s, c;
            sincospif((float)(f * t) * 0.125f, &s, &c);
            sr += irf[t] * c;
            si -= irf[t] * s;
        }
        // complex log (principal branch, same as jnp.log)
        float lr = 0.5f * logf(sr * sr + si * si);
        float li = atan2f(si, sr);
        rec[f] = lr;
        if (f >= 1 && f <= 7) rec[8 + f] = li;
    }

    float4* dst = &g_node_table[n * 4];
    dst[0] = make_float4(rec[0],  rec[1],  rec[2],  rec[3]);
    dst[1] = make_float4(rec[4],  rec[5],  rec[6],  rec[7]);
    dst[2] = make_float4(rec[8],  rec[9],  rec[10], rec[11]);
    dst[3] = make_float4(rec[12], rec[13], rec[14], rec[15]);
}

// ---------------------------------------------------------------------------
// Kernel B: segment starts from sorted path_idxs. Deterministic (each slot of
// g_seg_start written by exactly one thread).  seg_start[p] = lower_bound(p).
// ---------------------------------------------------------------------------
__global__ __launch_bounds__(256)
void seg_start_kernel(const int* __restrict__ path_idxs, int e_total, int n_paths) {
    int i = blockIdx.x * blockDim.x + threadIdx.x;
    if (i >= e_total) return;
    int cur = path_idxs[i];
    int prev = (i == 0) ? -1 : path_idxs[i - 1];
    for (int q = prev + 1; q <= cur; q++) {
        g_seg_start[q] = i;
    }
    if (i == e_total - 1) {
        for (int q = cur + 1; q <= n_paths; q++) {
            g_seg_start[q] = e_total;
        }
    }
}

// ---------------------------------------------------------------------------
// Kernel C: one thread per path. Gather+sum log-spectra, complex exp,
// analytic 16-pt irfft (with t <-> 16-t symmetry), relu, flip, normalize.
// ---------------------------------------------------------------------------
__global__ __launch_bounds__(128)
void agg_kernel(const int* __restrict__ path_nodes,
                float* __restrict__ out, int n_paths) {
    int p = blockIdx.x * blockDim.x + threadIdx.x;
    if (p >= n_paths) return;

    int s = g_seg_start[p];
    int e = g_seg_start[p + 1];

    float acc[16];
#pragma unroll
    for (int j = 0; j < 16; j++) acc[j] = 0.0f;

    for (int i = s; i < e; i++) {
        int n = __ldg(path_nodes + i);
        const float4* rec = &g_node_table[n * 4];
        float4 a = __ldg(rec + 0);
        float4 b = __ldg(rec + 1);
        float4 c = __ldg(rec + 2);
        float4 d = __ldg(rec + 3);
        acc[0] += a.x;  acc[1] += a.y;  acc[2]  += a.z;  acc[3]  += a.w;
        acc[4] += b.x;  acc[5] += b.y;  acc[6]  += b.z;  acc[7]  += b.w;
        acc[8] += c.x;  acc[9] += c.y;  acc[10] += c.z;  acc[11] += c.w;
        acc[12] += d.x; acc[13] += d.y; acc[14] += d.z;  acc[15] += d.w;
    }

    // complex exp of aggregated logs (CASCADE = 1)
    float Xr[F_C], Xi[F_C];
    Xr[0] = expf(acc[0]);
    Xi[0] = 0.0f;
    Xr[8] = expf(acc[8]);
    Xi[8] = 0.0f;
#pragma unroll
    for (int f = 1; f <= 7; f++) {
        float m = expf(acc[f]);
        float si, co;
        sincosf(acc[8 + f], &si, &co);
        Xr[f] = m * co;
        Xi[f] = m * si;
    }

    // irfft (n=16):
    // x[t] = (Xr0 + (-1)^t * Xr8 + 2*sum_{f=1..7} (Xr_f cos(pi f t/8) - Xi_f sin(pi f t/8))) / 16
    // Symmetry: x[16-t] uses (cs + ss) with identical base.
    float x[T_C];
#pragma unroll
    for (int t = 0; t <= 8; t++) {
        float s1, c1;
        sincospif((float)t * 0.125f, &s1, &c1);
        float cf = c1, sf = s1;   // cos/sin(pi*f*t/8) for f=1
        float cs = 0.0f, ss = 0.0f;
#pragma unroll
        for (int f = 1; f <= 7; f++) {
            cs += Xr[f] * cf;
            ss += Xi[f] * sf;
            float nc = cf * c1 - sf * s1;
            sf = cf * s1 + sf * c1;
            cf = nc;
        }
        float base = Xr[0] + ((t & 1) ? -Xr[8] : Xr[8]);
        float v1 = (base + 2.0f * (cs - ss)) * 0.0625f;
        if (t == 0) {
            x[0] = v1;
        } else if (t == 8) {
            x[8] = v1;
        } else {
            x[t] = v1;
            x[16 - t] = (base + 2.0f * (cs + ss)) * 0.0625f;
        }
    }

    // relu + sum
    float sum = 0.0f;
#pragma unroll
    for (int t = 0; t < T_C; t++) {
        x[t] = fmaxf(x[t], 0.0f);
        sum += x[t];
    }
    float inv_sum = 1.0f / sum;

    // flip + normalize, coalesced float4 stores (out[p*16 + j] = x[15-j]/sum)
    float4* o4 = reinterpret_cast<float4*>(out + (size_t)p * 16);
    o4[0] = make_float4(x[15] * inv_sum, x[14] * inv_sum, x[13] * inv_sum, x[12] * inv_sum);
    o4[1] = make_float4(x[11] * inv_sum, x[10] * inv_sum, x[9]  * inv_sum, x[8]  * inv_sum);
    o4[2] = make_float4(x[7]  * inv_sum, x[6]  * inv_sum, x[5]  * inv_sum, x[4]  * inv_sum);
    o4[3] = make_float4(x[3]  * inv_sum, x[2]  * inv_sum, x[1]  * inv_sum, x[0]  * inv_sum);
}

// ---------------------------------------------------------------------------
extern "C" void kernel_launch(void* const* d_in, const int* in_sizes, int n_in,
                              void* d_out, int out_size) {
    const float* params     = (const float*)d_in[0];
    const int*   path_idxs  = (const int*)d_in[1];
    const int*   path_nodes = (const int*)d_in[2];
    float*       out        = (float*)d_out;

    int n_nodes = in_sizes[0];
    int e_total = in_sizes[1];
    int n_paths = out_size / T_C;
    if (n_nodes > N_NODES_C) n_nodes = N_NODES_C;
    if (n_paths > N_PATHS_C) n_paths = N_PATHS_C;

    node_irf_kernel<<<(n_nodes + 127) / 128, 128>>>(params, n_nodes);
    seg_start_kernel<<<(e_total + 255) / 256, 256>>>(path_idxs, e_total, n_paths);
    agg_kernel<<<(n_paths + 127) / 128, 128>>>(path_nodes, out, n_paths);
}

// round 5
// speedup vs baseline: 1.3506x; 1.3506x over previous
#include <cuda_runtime.h>
#include <math.h>

#define N_NODES_C 100000
#define N_PATHS_C 1000000
#define T_C 16
#define F_C 9

// Node record: 16 floats (64B): [0..8] = Re(log X_f), [9..15] = Im(log X_f) f=1..7.
__device__ float4 g_node_table[N_NODES_C * 4];
__device__ int g_seg_start[N_PATHS_C + 1];

// ---------------------------------------------------------------------------
// Compile-time twiddles: cos(pi*k/8), sin(pi*k/8). After full unroll the
// switch folds to immediates -> FFMA-imm (rt_SMSP=1), zero MUFU.
// ---------------------------------------------------------------------------
__device__ __forceinline__ float COSPI16(int k) {
    switch (((k % 16) + 16) & 15) {
        case 0:  return  1.0f;
        case 1:  return  0.9238795325112867f;
        case 2:  return  0.7071067811865476f;
        case 3:  return  0.3826834323650898f;
        case 4:  return  0.0f;
        case 5:  return -0.3826834323650898f;
        case 6:  return -0.7071067811865476f;
        case 7:  return -0.9238795325112867f;
        case 8:  return -1.0f;
        case 9:  return -0.9238795325112867f;
        case 10: return -0.7071067811865476f;
        case 11: return -0.3826834323650898f;
        case 12: return  0.0f;
        case 13: return  0.3826834323650898f;
        case 14: return  0.7071067811865476f;
        default: return  0.9238795325112867f;
    }
}
__device__ __forceinline__ float SINPI16(int k) { return COSPI16(k - 4); }

// ---------------------------------------------------------------------------
// Kernel A: per-node IRF -> rfft(16) -> complex log, packed 64B per node.
// Single expf: irf[t] = inv_k * r^t with r = exp(-1/k).
// ---------------------------------------------------------------------------
__global__ __launch_bounds__(256)
void node_irf_kernel(const float* __restrict__ params, int n_nodes) {
    int n = blockIdx.x * blockDim.x + threadIdx.x;
    if (n >= n_nodes) return;

    float k = params[n] + 0.5f;
    float inv_k = 1.0f / k;
    float r = expf(-inv_k);

    float irf[T_C];
    irf[0] = inv_k;
#pragma unroll
    for (int t = 1; t < T_C; t++) irf[t] = irf[t - 1] * r;

    float rec[16];
#pragma unroll
    for (int f = 0; f < F_C; f++) {
        float sr = 0.0f, si = 0.0f;
#pragma unroll
        for (int t = 0; t < T_C; t++) {
            sr += irf[t] * COSPI16(f * t);
            si -= irf[t] * SINPI16(f * t);
        }
        float lr = 0.5f * logf(sr * sr + si * si);
        rec[f] = lr;
        if (f >= 1 && f <= 7) rec[8 + f] = atan2f(si, sr);
    }

    float4* dst = &g_node_table[n * 4];
    dst[0] = make_float4(rec[0],  rec[1],  rec[2],  rec[3]);
    dst[1] = make_float4(rec[4],  rec[5],  rec[6],  rec[7]);
    dst[2] = make_float4(rec[8],  rec[9],  rec[10], rec[11]);
    dst[3] = make_float4(rec[12], rec[13], rec[14], rec[15]);
}

// ---------------------------------------------------------------------------
// Kernel B: segment starts from sorted path_idxs (deterministic).
// ---------------------------------------------------------------------------
__global__ __launch_bounds__(256)
void seg_start_kernel(const int* __restrict__ path_idxs, int e_total, int n_paths) {
    int i = blockIdx.x * blockDim.x + threadIdx.x;
    if (i >= e_total) return;
    int cur = path_idxs[i];
    int prev = (i == 0) ? -1 : path_idxs[i - 1];
    for (int q = prev + 1; q <= cur; q++) g_seg_start[q] = i;
    if (i == e_total - 1) {
        for (int q = cur + 1; q <= n_paths; q++) g_seg_start[q] = e_total;
    }
}

// ---------------------------------------------------------------------------
// Kernel C: Phase 1 — 4 lanes per path cooperative gather (each lane owns one
// float4 of the 64B record -> fully-used 64B L1 wavefronts). Accumulators
// staged to padded smem. Phase 2 — one thread per path epilogue:
// complex exp, analytic 16-pt irfft (constant twiddles), relu, flip, norm.
// ---------------------------------------------------------------------------
#define AGG_TPB 256
#define PATHS_PER_BLK 256

__global__ __launch_bounds__(AGG_TPB)
void agg_kernel(const int* __restrict__ path_nodes,
                float* __restrict__ out, int n_paths) {
    __shared__ float s_acc[PATHS_PER_BLK][17];   // stride 17: conflict-free

    int tid = threadIdx.x;
    int block_base = blockIdx.x * PATHS_PER_BLK;
    int j = tid & 3;     // lane within 4-lane group
    int g = tid >> 2;    // group id 0..63

    // ---- Phase 1: gather (4 sub-phases x 64 paths) ----
#pragma unroll
    for (int sp = 0; sp < 4; sp++) {
        int lp = sp * 64 + g;             // local path index
        int p = block_base + lp;
        float4 acc = make_float4(0.0f, 0.0f, 0.0f, 0.0f);
        if (p < n_paths) {
            int s = g_seg_start[p];
            int e = g_seg_start[p + 1];
            for (int i = s; i < e; i++) {
                int n = __ldg(path_nodes + i);
                float4 v = __ldg(&g_node_table[n * 4 + j]);
                acc.x += v.x; acc.y += v.y; acc.z += v.z; acc.w += v.w;
            }
        }
        s_acc[lp][j * 4 + 0] = acc.x;
        s_acc[lp][j * 4 + 1] = acc.y;
        s_acc[lp][j * 4 + 2] = acc.z;
        s_acc[lp][j * 4 + 3] = acc.w;
    }
    __syncthreads();

    // ---- Phase 2: one thread per path ----
    int p = block_base + tid;
    if (p >= n_paths) return;

    float acc[16];
#pragma unroll
    for (int c = 0; c < 16; c++) acc[c] = s_acc[tid][c];

    // complex exp of aggregated logs (CASCADE = 1)
    float Xr[F_C], Xi[F_C];
    Xr[0] = expf(acc[0]);  Xi[0] = 0.0f;
    Xr[8] = expf(acc[8]);  Xi[8] = 0.0f;
#pragma unroll
    for (int f = 1; f <= 7; f++) {
        float m = expf(acc[f]);
        float si, co;
        sincosf(acc[8 + f], &si, &co);
        Xr[f] = m * co;
        Xi[f] = m * si;
    }

    // irfft (n=16) with t <-> 16-t symmetry, constant twiddles.
    float x[T_C];
#pragma unroll
    for (int t = 0; t <= 8; t++) {
        float cs = 0.0f, ss = 0.0f;
#pragma unroll
        for (int f = 1; f <= 7; f++) {
            cs += Xr[f] * COSPI16(f * t);
            ss += Xi[f] * SINPI16(f * t);
        }
        float base = Xr[0] + ((t & 1) ? -Xr[8] : Xr[8]);
        float v1 = (base + 2.0f * (cs - ss)) * 0.0625f;
        if (t == 0) {
            x[0] = v1;
        } else if (t == 8) {
            x[8] = v1;
        } else {
            x[t] = v1;
            x[16 - t] = (base + 2.0f * (cs + ss)) * 0.0625f;
        }
    }

    // relu + sum
    float sum = 0.0f;
#pragma unroll
    for (int t = 0; t < T_C; t++) {
        x[t] = fmaxf(x[t], 0.0f);
        sum += x[t];
    }
    float inv_sum = 1.0f / sum;

    // flip + normalize, coalesced float4 stores
    float4* o4 = reinterpret_cast<float4*>(out + (size_t)p * 16);
    o4[0] = make_float4(x[15] * inv_sum, x[14] * inv_sum, x[13] * inv_sum, x[12] * inv_sum);
    o4[1] = make_float4(x[11] * inv_sum, x[10] * inv_sum, x[9]  * inv_sum, x[8]  * inv_sum);
    o4[2] = make_float4(x[7]  * inv_sum, x[6]  * inv_sum, x[5]  * inv_sum, x[4]  * inv_sum);
    o4[3] = make_float4(x[3]  * inv_sum, x[2]  * inv_sum, x[1]  * inv_sum, x[0]  * inv_sum);
}

// ---------------------------------------------------------------------------
extern "C" void kernel_launch(void* const* d_in, const int* in_sizes, int n_in,
                              void* d_out, int out_size) {
    const float* params     = (const float*)d_in[0];
    const int*   path_idxs  = (const int*)d_in[1];
    const int*   path_nodes = (const int*)d_in[2];
    float*       out        = (float*)d_out;

    int n_nodes = in_sizes[0];
    int e_total = in_sizes[1];
    int n_paths = out_size / T_C;
    if (n_nodes > N_NODES_C) n_nodes = N_NODES_C;
    if (n_paths > N_PATHS_C) n_paths = N_PATHS_C;

    node_irf_kernel<<<(n_nodes + 255) / 256, 256>>>(params, n_nodes);
    seg_start_kernel<<<(e_total + 255) / 256, 256>>>(path_idxs, e_total, n_paths);
    agg_kernel<<<(n_paths + PATHS_PER_BLK - 1) / PATHS_PER_BLK, AGG_TPB>>>(path_nodes, out, n_paths);
}

// round 6
// speedup vs baseline: 1.3660x; 1.0114x over previous
#include <cuda_runtime.h>
#include <math.h>

#define N_NODES_C 100000
#define N_PATHS_C 1000000
#define T_C 16
#define F_C 9

// Node record: 16 floats (64B): [0..8] = Re(log X_f), [9..15] = Im(log X_f) f=1..7.
__device__ float4 g_node_table[N_NODES_C * 4];
__device__ int g_seg_start[N_PATHS_C + 1];

// ---------------------------------------------------------------------------
// Compile-time twiddles: cos(pi*k/8), sin(pi*k/8). Folds to FFMA immediates.
// ---------------------------------------------------------------------------
__device__ __forceinline__ float COSPI16(int k) {
    switch (((k % 16) + 16) & 15) {
        case 0:  return  1.0f;
        case 1:  return  0.9238795325112867f;
        case 2:  return  0.7071067811865476f;
        case 3:  return  0.3826834323650898f;
        case 4:  return  0.0f;
        case 5:  return -0.3826834323650898f;
        case 6:  return -0.7071067811865476f;
        case 7:  return -0.9238795325112867f;
        case 8:  return -1.0f;
        case 9:  return -0.9238795325112867f;
        case 10: return -0.7071067811865476f;
        case 11: return -0.3826834323650898f;
        case 12: return  0.0f;
        case 13: return  0.3826834323650898f;
        case 14: return  0.7071067811865476f;
        default: return  0.9238795325112867f;
    }
}
__device__ __forceinline__ float SINPI16(int k) { return COSPI16(k - 4); }

// ---------------------------------------------------------------------------
// Kernel A: per-node IRF -> rfft(16) -> complex log, packed 64B per node.
// ---------------------------------------------------------------------------
__global__ __launch_bounds__(256)
void node_irf_kernel(const float* __restrict__ params, int n_nodes) {
    int n = blockIdx.x * blockDim.x + threadIdx.x;
    if (n >= n_nodes) return;

    float k = params[n] + 0.5f;
    float inv_k = 1.0f / k;
    float r = expf(-inv_k);

    float irf[T_C];
    irf[0] = inv_k;
#pragma unroll
    for (int t = 1; t < T_C; t++) irf[t] = irf[t - 1] * r;

    float rec[16];
#pragma unroll
    for (int f = 0; f < F_C; f++) {
        float sr = 0.0f, si = 0.0f;
#pragma unroll
        for (int t = 0; t < T_C; t++) {
            sr += irf[t] * COSPI16(f * t);
            si -= irf[t] * SINPI16(f * t);
        }
        rec[f] = 0.5f * logf(sr * sr + si * si);
        if (f >= 1 && f <= 7) rec[8 + f] = atan2f(si, sr);
    }

    float4* dst = &g_node_table[n * 4];
    dst[0] = make_float4(rec[0],  rec[1],  rec[2],  rec[3]);
    dst[1] = make_float4(rec[4],  rec[5],  rec[6],  rec[7]);
    dst[2] = make_float4(rec[8],  rec[9],  rec[10], rec[11]);
    dst[3] = make_float4(rec[12], rec[13], rec[14], rec[15]);
}

// ---------------------------------------------------------------------------
// Kernel B: segment starts from sorted path_idxs (deterministic). shfl_up
// supplies the predecessor so each thread does only one global load.
// ---------------------------------------------------------------------------
__global__ __launch_bounds__(256)
void seg_start_kernel(const int* __restrict__ path_idxs, int e_total, int n_paths) {
    int i = blockIdx.x * blockDim.x + threadIdx.x;
    if (i >= e_total) return;
    int cur = path_idxs[i];
    int prev = __shfl_up_sync(0xffffffffu, cur, 1);
    if ((threadIdx.x & 31) == 0) {
        prev = (i == 0) ? -1 : __ldg(path_idxs + i - 1);
    }
    for (int q = prev + 1; q <= cur; q++) g_seg_start[q] = i;
    if (i == e_total - 1) {
        for (int q = cur + 1; q <= n_paths; q++) g_seg_start[q] = e_total;
    }
}

// ---------------------------------------------------------------------------
// Kernel C: Phase 1 — 4 lanes per path, 8-entry chunks with predicated loads:
// 8 independent idx loads then 8 independent record loads (MLP=8 per lane,
// no pointer-chase serialization, no tail-loop divergence). Phase 2 — one
// thread per path epilogue via padded smem staging.
// ---------------------------------------------------------------------------
#define AGG_TPB 256
#define PATHS_PER_BLK 256
#define CHUNK 8

__global__ __launch_bounds__(AGG_TPB, 4)
void agg_kernel(const int* __restrict__ path_nodes,
                float* __restrict__ out, int n_paths) {
    __shared__ float s_acc[PATHS_PER_BLK][17];   // stride 17: conflict-free

    int tid = threadIdx.x;
    int block_base = blockIdx.x * PATHS_PER_BLK;
    int j = tid & 3;     // float4 slot within 64B record
    int g = tid >> 2;    // group id 0..63

    // ---- Phase 1: gather (4 sub-phases x 64 paths) ----
#pragma unroll
    for (int sp = 0; sp < 4; sp++) {
        int lp = sp * 64 + g;
        int p = block_base + lp;
        float4 acc = make_float4(0.0f, 0.0f, 0.0f, 0.0f);
        if (p < n_paths) {
            int s = g_seg_start[p];
            int e = g_seg_start[p + 1];
            for (int i = s; i < e; i += CHUNK) {
                int nn[CHUNK];
#pragma unroll
                for (int kk = 0; kk < CHUNK; kk++) {
                    nn[kk] = (i + kk < e) ? __ldg(path_nodes + i + kk) : -1;
                }
                float4 vv[CHUNK];
#pragma unroll
                for (int kk = 0; kk < CHUNK; kk++) {
                    vv[kk] = (nn[kk] >= 0)
                        ? __ldg(&g_node_table[nn[kk] * 4 + j])
                        : make_float4(0.0f, 0.0f, 0.0f, 0.0f);
                }
#pragma unroll
                for (int kk = 0; kk < CHUNK; kk++) {
                    acc.x += vv[kk].x; acc.y += vv[kk].y;
                    acc.z += vv[kk].z; acc.w += vv[kk].w;
                }
            }
        }
        s_acc[lp][j * 4 + 0] = acc.x;
        s_acc[lp][j * 4 + 1] = acc.y;
        s_acc[lp][j * 4 + 2] = acc.z;
        s_acc[lp][j * 4 + 3] = acc.w;
    }
    __syncthreads();

    // ---- Phase 2: one thread per path ----
    int p = block_base + tid;
    if (p >= n_paths) return;

    float acc[16];
#pragma unroll
    for (int c = 0; c < 16; c++) acc[c] = s_acc[tid][c];

    // complex exp of aggregated logs (CASCADE = 1)
    float Xr[F_C], Xi[F_C];
    Xr[0] = expf(acc[0]);  Xi[0] = 0.0f;
    Xr[8] = expf(acc[8]);  Xi[8] = 0.0f;
#pragma unroll
    for (int f = 1; f <= 7; f++) {
        float m = expf(acc[f]);
        float si, co;
        sincosf(acc[8 + f], &si, &co);
        Xr[f] = m * co;
        Xi[f] = m * si;
    }

    // irfft (n=16) with t <-> 16-t symmetry, constant twiddles.
    float x[T_C];
#pragma unroll
    for (int t = 0; t <= 8; t++) {
        float cs = 0.0f, ss = 0.0f;
#pragma unroll
        for (int f = 1; f <= 7; f++) {
            cs += Xr[f] * COSPI16(f * t);
            ss += Xi[f] * SINPI16(f * t);
        }
        float base = Xr[0] + ((t & 1) ? -Xr[8] : Xr[8]);
        float v1 = (base + 2.0f * (cs - ss)) * 0.0625f;
        if (t == 0) {
            x[0] = v1;
        } else if (t == 8) {
            x[8] = v1;
        } else {
            x[t] = v1;
            x[16 - t] = (base + 2.0f * (cs + ss)) * 0.0625f;
        }
    }

    // relu + sum
    float sum = 0.0f;
#pragma unroll
    for (int t = 0; t < T_C; t++) {
        x[t] = fmaxf(x[t], 0.0f);
        sum += x[t];
    }
    float inv_sum = 1.0f / sum;

    // flip + normalize, coalesced float4 stores
    float4* o4 = reinterpret_cast<float4*>(out + (size_t)p * 16);
    o4[0] = make_float4(x[15] * inv_sum, x[14] * inv_sum, x[13] * inv_sum, x[12] * inv_sum);
    o4[1] = make_float4(x[11] * inv_sum, x[10] * inv_sum, x[9]  * inv_sum, x[8]  * inv_sum);
    o4[2] = make_float4(x[7]  * inv_sum, x[6]  * inv_sum, x[5]  * inv_sum, x[4]  * inv_sum);
    o4[3] = make_float4(x[3]  * inv_sum, x[2]  * inv_sum, x[1]  * inv_sum, x[0]  * inv_sum);
}

// ---------------------------------------------------------------------------
extern "C" void kernel_launch(void* const* d_in, const int* in_sizes, int n_in,
                              void* d_out, int out_size) {
    const float* params     = (const float*)d_in[0];
    const int*   path_idxs  = (const int*)d_in[1];
    const int*   path_nodes = (const int*)d_in[2];
    float*       out        = (float*)d_out;

    int n_nodes = in_sizes[0];
    int e_total = in_sizes[1];
    int n_paths = out_size / T_C;
    if (n_nodes > N_NODES_C) n_nodes = N_NODES_C;
    if (n_paths > N_PATHS_C) n_paths = N_PATHS_C;

    node_irf_kernel<<<(n_nodes + 255) / 256, 256>>>(params, n_nodes);
    seg_start_kernel<<<(e_total + 255) / 256, 256>>>(path_idxs, e_total, n_paths);
    agg_kernel<<<(n_paths + PATHS_PER_BLK - 1) / PATHS_PER_BLK, AGG_TPB>>>(path_nodes, out, n_paths);
}

// round 11
// speedup vs baseline: 1.4230x; 1.0417x over previous
#include <cuda_runtime.h>
#include <math.h>

#define N_NODES_C 100000
#define N_PATHS_C 1000000
#define T_C 16
#define F_C 9

#define QSCALE 16384.0f
#define QINV   (1.0f / 16384.0f)

// Node record: 16 x int16 (32B, one L2 sector): [0..8]=Re(log X_f)*2^14,
// [9..15]=Im(log X_f)*2^14 for f=1..7. 32B-aligned -> never straddles a line.
__device__ int2 g_tab[N_NODES_C * 4];     // record n = g_tab[4n .. 4n+3]
__device__ int g_seg_start[N_PATHS_C + 1];

// ---------------------------------------------------------------------------
// Compile-time twiddles: cos(pi*k/8), sin(pi*k/8). Folds to FFMA immediates.
// ---------------------------------------------------------------------------
__device__ __forceinline__ float COSPI16(int k) {
    switch (((k % 16) + 16) & 15) {
        case 0:  return  1.0f;
        case 1:  return  0.9238795325112867f;
        case 2:  return  0.7071067811865476f;
        case 3:  return  0.3826834323650898f;
        case 4:  return  0.0f;
        case 5:  return -0.3826834323650898f;
        case 6:  return -0.7071067811865476f;
        case 7:  return -0.9238795325112867f;
        case 8:  return -1.0f;
        case 9:  return -0.9238795325112867f;
        case 10: return -0.7071067811865476f;
        case 11: return -0.3826834323650898f;
        case 12: return  0.0f;
        case 13: return  0.3826834323650898f;
        case 14: return  0.7071067811865476f;
        default: return  0.9238795325112867f;
    }
}
__device__ __forceinline__ float SINPI16(int k) { return COSPI16(k - 4); }

__device__ __forceinline__ int q16(float v) {
    int x = __float2int_rn(v * QSCALE);
    x = max(-32768, min(32767, x));
    return x;
}
__device__ __forceinline__ int pack16(int a, int b) {
    return (a & 0xFFFF) | (b << 16);
}

// ---------------------------------------------------------------------------
// Kernel A: per-node log-spectrum via geometric closed form:
//   X_f = inv_k*(1-r^16) / (1 - r*e^{-i*pi*f/8}),  r = exp(-1/k)
//   Re log X_f = C - 0.5*log(dre^2+dim^2),  Im log X_f = -atan2(dim, dre)
// Quantized to int16*2^14, packed 32B per node.
// Bound check: k in [0.5,1.5) -> |Re| <= ~1.41, |Im| <= ~0.54, well inside
// int16 range (+-2.0) at 2^-14 resolution.
// ---------------------------------------------------------------------------
__global__ __launch_bounds__(256)
void node_irf_kernel(const float* __restrict__ params, int n_nodes) {
    int n = blockIdx.x * blockDim.x + threadIdx.x;
    if (n >= n_nodes) return;

    float k = params[n] + 0.5f;
    float inv_k = 1.0f / k;
    float r = expf(-inv_k);
    float r2 = r * r, r4 = r2 * r2, r8 = r4 * r4, r16 = r8 * r8;
    float C = logf(inv_k * (1.0f - r16));

    int q[16];
    q[0] = q16(C - logf(1.0f - r));       // f=0
    q[8] = q16(C - logf(1.0f + r));       // f=8 (Nyquist)
#pragma unroll
    for (int f = 1; f <= 7; f++) {
        float dre = 1.0f - r * COSPI16(f);
        float dim = r * SINPI16(f);
        q[f]     = q16(C - 0.5f * logf(dre * dre + dim * dim));
        q[8 + f] = q16(-atan2f(dim, dre));
    }

    int4* dst = reinterpret_cast<int4*>(&g_tab[n * 4]);
    dst[0] = make_int4(pack16(q[0],  q[1]),  pack16(q[2],  q[3]),
                       pack16(q[4],  q[5]),  pack16(q[6],  q[7]));
    dst[1] = make_int4(pack16(q[8],  q[9]),  pack16(q[10], q[11]),
                       pack16(q[12], q[13]), pack16(q[14], q[15]));
}

// ---------------------------------------------------------------------------
// Kernel B: segment starts from sorted path_idxs (deterministic).
// ---------------------------------------------------------------------------
__global__ __launch_bounds__(256)
void seg_start_kernel(const int* __restrict__ path_idxs, int e_total, int n_paths) {
    int i = blockIdx.x * blockDim.x + threadIdx.x;
    if (i >= e_total) return;
    int cur = path_idxs[i];
    int prev = __shfl_up_sync(0xffffffffu, cur, 1);
    if ((threadIdx.x & 31) == 0) {
        prev = (i == 0) ? -1 : __ldg(path_idxs + i - 1);
    }
    for (int q = prev + 1; q <= cur; q++) g_seg_start[q] = i;
    if (i == e_total - 1) {
        for (int q = cur + 1; q <= n_paths; q++) g_seg_start[q] = e_total;
    }
}

// ---------------------------------------------------------------------------
// Kernel C: Phase 1 — 4 lanes per path; lane j loads int2 (8B) slot j of the
// 32B record (one sector, one wavefront per record). Exact int32 accumulation
// (deterministic; |sum| < 25 entries * 32768 << 2^31). Phase 2 — one thread
// per path: dequant, complex exp, analytic 16-pt irfft (constant twiddles),
// relu, flip, normalize.
// ---------------------------------------------------------------------------
#define AGG_TPB 256
#define PATHS_PER_BLK 256
#define CHUNK 8

__global__ __launch_bounds__(AGG_TPB, 4)
void agg_kernel(const int* __restrict__ path_nodes,
                float* __restrict__ out, int n_paths) {
    __shared__ int s_acc[PATHS_PER_BLK][17];   // stride 17: conflict-free

    int tid = threadIdx.x;
    int block_base = blockIdx.x * PATHS_PER_BLK;
    int j = tid & 3;     // int2 slot within 32B record
    int g = tid >> 2;    // group id 0..63

    const int2* tab = g_tab;

    // ---- Phase 1: gather (4 sub-phases x 64 paths) ----
#pragma unroll
    for (int sp = 0; sp < 4; sp++) {
        int lp = sp * 64 + g;
        int p = block_base + lp;
        int a0 = 0, a1 = 0, a2 = 0, a3 = 0;
        if (p < n_paths) {
            int s = g_seg_start[p];
            int e = g_seg_start[p + 1];
            for (int i = s; i < e; i += CHUNK) {
                int nn[CHUNK];
#pragma unroll
                for (int kk = 0; kk < CHUNK; kk++) {
                    nn[kk] = (i + kk < e) ? __ldg(path_nodes + i + kk) : -1;
                }
                int2 vv[CHUNK];
#pragma unroll
                for (int kk = 0; kk < CHUNK; kk++) {
                    vv[kk] = (nn[kk] >= 0) ? __ldg(tab + nn[kk] * 4 + j)
                                           : make_int2(0, 0);
                }
#pragma unroll
                for (int kk = 0; kk < CHUNK; kk++) {
                    a0 += (int)(short)vv[kk].x;
                    a1 += vv[kk].x >> 16;
                    a2 += (int)(short)vv[kk].y;
                    a3 += vv[kk].y >> 16;
                }
            }
        }
        s_acc[lp][j * 4 + 0] = a0;
        s_acc[lp][j * 4 + 1] = a1;
        s_acc[lp][j * 4 + 2] = a2;
        s_acc[lp][j * 4 + 3] = a3;
    }
    __syncthreads();

    // ---- Phase 2: one thread per path ----
    int p = block_base + tid;
    if (p >= n_paths) return;

    float acc[16];
#pragma unroll
    for (int c = 0; c < 16; c++) acc[c] = (float)s_acc[tid][c] * QINV;

    // complex exp of aggregated logs (CASCADE = 1)
    float Xr[F_C], Xi[F_C];
    Xr[0] = expf(acc[0]);  Xi[0] = 0.0f;
    Xr[8] = expf(acc[8]);  Xi[8] = 0.0f;
#pragma unroll
    for (int f = 1; f <= 7; f++) {
        float m = expf(acc[f]);
        float si, co;
        sincosf(acc[8 + f], &si, &co);
        Xr[f] = m * co;
        Xi[f] = m * si;
    }

    // irfft (n=16) with t <-> 16-t symmetry, constant twiddles.
    float x[T_C];
#pragma unroll
    for (int t = 0; t <= 8; t++) {
        float cs = 0.0f, ss = 0.0f;
#pragma unroll
        for (int f = 1; f <= 7; f++) {
            cs += Xr[f] * COSPI16(f * t);
            ss += Xi[f] * SINPI16(f * t);
        }
        float base = Xr[0] + ((t & 1) ? -Xr[8] : Xr[8]);
        float v1 = (base + 2.0f * (cs - ss)) * 0.0625f;
        if (t == 0) {
            x[0] = v1;
        } else if (t == 8) {
            x[8] = v1;
        } else {
            x[t] = v1;
            x[16 - t] = (base + 2.0f * (cs + ss)) * 0.0625f;
        }
    }

    // relu + sum
    float sum = 0.0f;
#pragma unroll
    for (int t = 0; t < T_C; t++) {
        x[t] = fmaxf(x[t], 0.0f);
        sum += x[t];
    }
    float inv_sum = 1.0f / sum;

    // flip + normalize, coalesced float4 stores
    float4* o4 = reinterpret_cast<float4*>(out + (size_t)p * 16);
    o4[0] = make_float4(x[15] * inv_sum, x[14] * inv_sum, x[13] * inv_sum, x[12] * inv_sum);
    o4[1] = make_float4(x[11] * inv_sum, x[10] * inv_sum, x[9]  * inv_sum, x[8]  * inv_sum);
    o4[2] = make_float4(x[7]  * inv_sum, x[6]  * inv_sum, x[5]  * inv_sum, x[4]  * inv_sum);
    o4[3] = make_float4(x[3]  * inv_sum, x[2]  * inv_sum, x[1]  * inv_sum, x[0]  * inv_sum);
}

// ---------------------------------------------------------------------------
extern "C" void kernel_launch(void* const* d_in, const int* in_sizes, int n_in,
                              void* d_out, int out_size) {
    const float* params     = (const float*)d_in[0];
    const int*   path_idxs  = (const int*)d_in[1];
    const int*   path_nodes = (const int*)d_in[2];
    float*       out        = (float*)d_out;

    int n_nodes = in_sizes[0];
    int e_total = in_sizes[1];
    int n_paths = out_size / T_C;
    if (n_nodes > N_NODES_C) n_nodes = N_NODES_C;
    if (n_paths > N_PATHS_C) n_paths = N_PATHS_C;

    node_irf_kernel<<<(n_nodes + 255) / 256, 256>>>(params, n_nodes);
    seg_start_kernel<<<(e_total + 255) / 256, 256>>>(path_idxs, e_total, n_paths);
    agg_kernel<<<(n_paths + PATHS_PER_BLK - 1) / PATHS_PER_BLK, AGG_TPB>>>(path_nodes, out, n_paths);
}